// round 15
// baseline (speedup 1.0000x reference)
#include <cuda_runtime.h>
#include <cuda_fp16.h>
#include <cstdint>

// ---------------------------------------------------------------------------
// KronFTLinear, fp16 mma.sync GEMMs (m16n8k16, f32 accum):
//   * base+delta FUSED into one K-concat GEMM:
//       out[row, 2n+z] = [xh | Z_z] @ [whp_z | W2]^T + b     (K = 8192)
//   * trig-GEMM scale 150 folded into stored W2.
// GEMM engine (R15): 128x128 CTA tile, 4 warps of 64x64, 128 threads,
// BK=64 chunks (two 32-col sub-tiles), 2-stage double buffer with ONE
// __syncthreads per 64-K chunk (next load issued before compute), 2 CTAs/SM,
// L2 raster swizzle, parity batch z folded into fastest launch dim.
// ---------------------------------------------------------------------------

#define DD 4096
#define OO 4096
#define HALF_D 2048
#define NFP 1000
#define ROWS 8192
#define NGATE 819

typedef long long ll;

// ---------------- device scratch (no allocation allowed) -------------------
__device__ int   g_idx32[2*NFP];
__device__ int   g_gidx32[NGATE];
__device__ float g_gate_m[2*DD];
__device__ __half g_Pms[2ll*HALF_D*HALF_D];  // trig A-factor [p][m][k]
__device__ __half g_Qns[2ll*HALF_D*HALF_D];  // trig B-factor [p][n][k]
__device__ __half g_W2s[(ll)HALF_D*DD];      // 150 * A-matrix stack (fp16)
__device__ __half g_Zs[2ll*ROWS*DD];         // gated mixed x (fp16) [i][row][*]
__device__ __half g_xh[(ll)ROWS*DD];         // fp16 x
__device__ __half g_whp[(ll)OO*DD];          // fp16 base_w, parity-packed [z][n][k]

// ---------------- PTX helpers ----------------------------------------------
__device__ __forceinline__ uint32_t smem_u32(const void* p) {
    uint32_t a;
    asm("{ .reg .u64 t; cvta.to.shared.u64 t, %1; cvt.u32.u64 %0, t; }" : "=r"(a) : "l"(p));
    return a;
}
#define CP_ASYNC16(dst, src) \
    asm volatile("cp.async.cg.shared.global [%0], [%1], 16;" :: "r"(dst), "l"(src) : "memory")
#define CP_COMMIT() asm volatile("cp.async.commit_group;" ::: "memory")

#define LDSM_X4(r0, r1, r2, r3, addr) \
    asm volatile("ldmatrix.sync.aligned.m8n8.x4.shared.b16 {%0,%1,%2,%3}, [%4];" \
        : "=r"(r0), "=r"(r1), "=r"(r2), "=r"(r3) : "r"(addr))

#define MMA16816(c, a, b) \
    asm volatile("mma.sync.aligned.m16n8k16.row.col.f32.f16.f16.f32 " \
        "{%0,%1,%2,%3}, {%4,%5,%6,%7}, {%8,%9}, {%0,%1,%2,%3};" \
        : "+f"((c)[0]), "+f"((c)[1]), "+f"((c)[2]), "+f"((c)[3]) \
        : "r"((a)[0]), "r"((a)[1]), "r"((a)[2]), "r"((a)[3]), \
          "r"((b)[0]), "r"((b)[1]))

// ---------------- index decode: sniff int32 vs int64 -----------------------
__global__ void k_decode_idx(const int* __restrict__ idx_raw,
                             const int* __restrict__ gidx_raw) {
    __shared__ int nz;
    if (threadIdx.x == 0) nz = 0;
    __syncthreads();
    for (int k = threadIdx.x; k < NFP/2; k += 256)
        if (idx_raw[2*k + 1] != 0) atomicAdd(&nz, 1);
    __syncthreads();
    bool is64 = (nz == 0);
    for (int k = threadIdx.x; k < 2*NFP; k += 256)
        g_idx32[k] = is64 ? idx_raw[2*k] : idx_raw[k];
    for (int k = threadIdx.x; k < NGATE; k += 256)
        g_gidx32[k] = is64 ? gidx_raw[2*k] : gidx_raw[k];
}

// ---------------- gate matrix ----------------------------------------------
__global__ void k_gate_m(const float* __restrict__ gate_param) {
    __shared__ float tab[DD];
    __shared__ int   gc[NGATE];
    __shared__ float gg[NGATE], gs[NGATE];
    for (int t = threadIdx.x; t < DD; t += 256)
        tab[t] = cospif(t * (1.0f/2048.0f));
    for (int k = threadIdx.x; k < NGATE; k += 256) {
        int v = g_gidx32[k];
        int r = v >> 12;
        gc[k] = v & 4095;
        float g = gate_param[k];
        gg[k] = g;
        gs[k] = r ? -g : g;
    }
    __syncthreads();
    int d = blockIdx.x * 256 + threadIdx.x;
    float a0 = 0.f, a1 = 0.f;
    for (int k = 0; k < NGATE; k++) {
        int t = (d * gc[k]) & 4095;
        float co = tab[t];
        a0 += gg[k] * co;
        a1 += gs[k] * co;
    }
    g_gate_m[d]      = a0 * (1.0f/8192.0f);
    g_gate_m[DD + d] = a1 * (1.0f/8192.0f);
}

// ---------------- fused: gate weights + fp16 x cast + Z build --------------
__global__ __launch_bounds__(128)
void k_gate_z(const float* __restrict__ x, const float* __restrict__ Blist) {
    int row = blockIdx.x;
    int tid = threadIdx.x;
    const float2* xr = (const float2*)(x + (ll)row * DD);
    const float2* gm0 = (const float2*)g_gate_m;
    const float2* gm1 = (const float2*)(g_gate_m + DD);
    __half2* xhr = (__half2*)(g_xh + (ll)row * DD);

    float2 xv[16];
    float t0 = 0.f, t1 = 0.f;
    #pragma unroll
    for (int i = 0; i < 16; i++) {
        int d2 = tid + i*128;
        float2 v = xr[d2];
        xv[i] = v;
        xhr[d2] = __floats2half2_rn(v.x, v.y);
        float2 m0 = gm0[d2], m1 = gm1[d2];
        t0 += v.x*m0.x + v.y*m0.y;
        t1 += v.x*m1.x + v.y*m1.y;
    }

    __shared__ float s0[128], s1[128];
    __shared__ float sg[2];
    s0[tid] = t0; s1[tid] = t1;
    __syncthreads();
    for (int o = 64; o > 0; o >>= 1) {
        if (tid < o) { s0[tid] += s0[tid + o]; s1[tid] += s1[tid + o]; }
        __syncthreads();
    }
    if (tid == 0) {
        float g1 = 1.0f / (1.0f + expf(-(s1[0] - s0[0])));
        sg[0] = 1.0f - g1;
        sg[1] = g1;
    }
    __syncthreads();
    float g0 = sg[0], g1 = sg[1];

    float b0 = Blist[0], b1 = Blist[1], b2 = Blist[2], b3 = Blist[3];
    float b4 = Blist[4], b5 = Blist[5], b6 = Blist[6], b7 = Blist[7];
    const ll IOFF = (ll)ROWS * DD;
    ll base = (ll)row * DD;
    #pragma unroll
    for (int i = 0; i < 16; i++) {
        int d2 = tid + i*128;
        float xx = xv[i].x, yy = xv[i].y;
        g_Zs[base + d2]                 = __float2half(g0 * (b0*xx + b1*yy)); // i=0,p=0
        g_Zs[base + HALF_D + d2]        = __float2half(g1 * (b4*xx + b5*yy)); // i=0,p=1
        g_Zs[IOFF + base + d2]          = __float2half(g0 * (b2*xx + b3*yy)); // i=1,p=0
        g_Zs[IOFF + base + HALF_D + d2] = __float2half(g1 * (b6*xx + b7*yy)); // i=1,p=1
    }
}

// ---------------- trig factors, fp16 ----------------------------------------
__global__ void k_fill_trig(const float* __restrict__ spectrum) {
    __shared__ float tc[HALF_D], ts[HALF_D];
    __shared__ int   rr[NFP], cc[NFP];
    __shared__ float ss[NFP];
    int p = blockIdx.y;
    for (int t = threadIdx.x; t < HALF_D; t += 256) {
        float s, c;
        sincospif(t * (1.0f/1024.0f), &s, &c);
        tc[t] = c; ts[t] = s;
    }
    for (int k = threadIdx.x; k < NFP; k += 256) {
        int v = g_idx32[p*NFP + k];
        rr[k] = v >> 11;
        cc[k] = v & 2047;
        ss[k] = spectrum[p*NFP + k];
    }
    __syncthreads();
    int v0 = blockIdx.x * 8;
    for (int vi = 0; vi < 8; vi++) {
        int v = v0 + vi;
        ll base = ((ll)(p*HALF_D + v)) * HALF_D;
        for (int k = threadIdx.x; k < NFP; k += 256) {
            int tm = (v * rr[k]) & 2047;
            int tn = (v * cc[k]) & 2047;
            float s = ss[k];
            g_Pms[base + k]       = __float2half(s * tc[tm]);
            g_Pms[base + NFP + k] = __float2half(s * ts[tm]);
            g_Qns[base + k]       = __float2half(tc[tn]);
            g_Qns[base + NFP + k] = __float2half(-ts[tn]);
        }
        for (int k = 2*NFP + threadIdx.x; k < HALF_D; k += 256) {
            __half z = __float2half(0.f);
            g_Pms[base + k] = z;
            g_Qns[base + k] = z;
        }
    }
}

// ---------------- fp32 w -> fp16, parity-packed: whp[z][n][k] = w[2n+z][k] --
__global__ void k_cast_wp(const float* __restrict__ src) {
    ll i = (ll)blockIdx.x * 256 + threadIdx.x;
    int o = (int)(i >> 12);
    int k = (int)(i & 4095);
    int z = o & 1, n = o >> 1;
    g_whp[(ll)z*HALF_D*DD + (ll)n*DD + k] = __float2half(src[i]);
}

// ---------------- fp16 tensor-core GEMM with K-concat dual source ----------
// C = alpha * [A | A2] @ [B | B2]^T (+bias).  Source switches at Ksplit
// (multiple of 64).  128x128 CTA tile, 4 warps (2x2) of 64x64, 128 threads.
// BK=64 chunks as two 32-col sub-tiles; 2-stage double buffer, ONE
// __syncthreads per chunk (next chunk's cp.async issued before compute).
// Batch z folded into blockIdx.x (fastest).  Output (m,n,z) at
// C[m*ldc + n*cstride + z*czoff]; bias indexed bias[n*cstride + z*czoff].
#define SUB_BYTES   20480u      // A(10240B)+B(10240B) per 32-col sub-tile
#define STAGE_BYTES 40960u      // two sub-tiles = BK=64 chunk
#define SMEM_DYN (2*STAGE_BYTES)
#define GRP 8                   // m-tiles per L2 group

__global__ __launch_bounds__(128, 2)
void tgemm(const __half* __restrict__ A,  int lda, ll sAz,
           const __half* __restrict__ A2, ll sA2z,
           const __half* __restrict__ B,  int ldb, ll sBz,
           const __half* __restrict__ B2, ll sB2z,
           void* __restrict__ Cv, int ldc, int cstride, int czoff,
           const float* __restrict__ bias, float alpha,
           int Kp, int Ksplit, int zshift, int out_half)
{
    extern __shared__ char smem[];
    uint32_t sbase = smem_u32(smem);
    int tid = threadIdx.x, wid = tid >> 5, lane = tid & 31;
    int warpM = wid >> 1;          // 0..1  (64 rows)
    int warpN = wid & 1;           // 0..1  (64 cols)

    // z folded into fastest launch dim; then GRP raster swizzle on tile id
    int rawbid = blockIdx.y * gridDim.x + blockIdx.x;
    int z   = rawbid & ((1 << zshift) - 1);
    int fl2 = rawbid >> zshift;
    int tpg = GRP * gridDim.y;
    int grp = fl2 / tpg;
    int rem = fl2 - grp * tpg;
    int mt  = grp * GRP + (rem % GRP);
    int nt  = rem / GRP;

    ll m0 = (ll)mt * 128;
    ll n0 = (ll)nt * 128;
    const __half* Ab  = A  + (ll)z*sAz  + m0*lda;
    const __half* Ab2 = A2 + (ll)z*sA2z + m0*lda;
    const __half* Bb  = B  + (ll)z*sBz  + n0*ldb;
    const __half* Bb2 = B2 + (ll)z*sB2z + n0*ldb;

    float acc[4][8][4];
    #pragma unroll
    for (int i = 0; i < 4; i++)
        #pragma unroll
        for (int j = 0; j < 8; j++)
            #pragma unroll
            for (int q = 0; q < 4; q++) acc[i][j][q] = 0.f;

    int ldr = tid >> 2;            // 0..31
    int ldc8 = (tid & 3) * 8;      // 0,8,16,24

    int aRow = warpM*64 + (lane & 15);
    int aCsel = (lane >> 4) * 8;
    int bRowOff = (lane & 7) + ((lane >> 4) << 3);
    int bCsel = ((lane >> 3) & 1) * 8;

    int NP = Kp >> 6;              // BK=64 chunks

    // Load one BK=64 chunk (two 32-col sub-tiles) into stage stg.
    // k0 is uniform across the CTA and 64-aligned; sub-chunks share a source.
    #define TG_LOAD(stg, k0) do {                                              \
        _Pragma("unroll")                                                      \
        for (int _s = 0; _s < 2; _s++) {                                       \
            int _k = (k0) + _s*32;                                             \
            const __half* _As; const __half* _Bs; int _ko;                     \
            if (_k < Ksplit) { _As = Ab;  _Bs = Bb;  _ko = _k; }               \
            else             { _As = Ab2; _Bs = Bb2; _ko = _k - Ksplit; }      \
            uint32_t _sb = sbase + (uint32_t)(stg)*STAGE_BYTES                 \
                                 + (uint32_t)_s*SUB_BYTES;                     \
            uint32_t _da = _sb + (uint32_t)ldr*80 + (uint32_t)ldc8*2;          \
            uint32_t _db = _da + 10240u;                                       \
            _Pragma("unroll")                                                  \
            for (int _h = 0; _h < 4; _h++) {                                   \
                CP_ASYNC16(_da + _h*32*80, _As + (ll)(ldr + _h*32)*lda + _ko + ldc8); \
                CP_ASYNC16(_db + _h*32*80, _Bs + (ll)(ldr + _h*32)*ldb + _ko + ldc8); \
            }                                                                  \
        }                                                                      \
        CP_COMMIT();                                                           \
    } while (0)

    TG_LOAD(0, 0);

    int stg = 0;
    for (int kc = 0; kc < NP; kc++) {
        asm volatile("cp.async.wait_group 0;" ::: "memory");  // chunk kc landed
        __syncthreads();   // publishes chunk kc; all warps done reading stage stg^1
        if (kc + 1 < NP) TG_LOAD(stg ^ 1, (kc + 1) * 64);     // overlaps compute below

        #pragma unroll
        for (int sub = 0; sub < 2; sub++) {
            uint32_t sao = sbase + (uint32_t)stg*STAGE_BYTES + (uint32_t)sub*SUB_BYTES;
            uint32_t sbo = sao + 10240u;
            #pragma unroll
            for (int ks = 0; ks < 32; ks += 16) {
                uint32_t af[4][4];
                #pragma unroll
                for (int mi = 0; mi < 4; mi++) {
                    uint32_t ad = sao + (uint32_t)(aRow + mi*16)*80 + (uint32_t)(ks + aCsel)*2;
                    LDSM_X4(af[mi][0], af[mi][1], af[mi][2], af[mi][3], ad);
                }
                uint32_t bf[8][2];
                #pragma unroll
                for (int nj = 0; nj < 4; nj++) {
                    uint32_t bd = sbo + (uint32_t)(warpN*64 + nj*16 + bRowOff)*80
                                      + (uint32_t)(ks + bCsel)*2;
                    uint32_t r0, r1, r2, r3;
                    LDSM_X4(r0, r1, r2, r3, bd);
                    bf[nj*2][0] = r0;   bf[nj*2][1] = r1;
                    bf[nj*2+1][0] = r2; bf[nj*2+1][1] = r3;
                }
                #pragma unroll
                for (int mi = 0; mi < 4; mi++)
                    #pragma unroll
                    for (int ni = 0; ni < 8; ni++)
                        MMA16816(acc[mi][ni], af[mi], bf[ni]);
            }
        }
        stg ^= 1;
    }

    // epilogue
    int gID = lane >> 2, tig = lane & 3;
    #pragma unroll
    for (int mi = 0; mi < 4; mi++) {
        #pragma unroll
        for (int h = 0; h < 2; h++) {
            ll row = m0 + warpM*64 + mi*16 + gID + h*8;
            ll rbase = row * (ll)ldc + (ll)z * czoff;
            #pragma unroll
            for (int ni = 0; ni < 8; ni++) {
                ll col0 = n0 + warpN*64 + ni*8 + tig*2;
                #pragma unroll
                for (int q = 0; q < 2; q++) {
                    ll col = col0 + q;
                    float v = acc[mi][ni][h*2 + q] * alpha;
                    ll coff = col * cstride + (ll)z * czoff;
                    if (bias) v += bias[coff];
                    ll off = rbase + col * cstride;
                    if (out_half) {
                        ((__half*)Cv)[off] = __float2half(v);
                    } else {
                        ((float*)Cv)[off] = v;
                    }
                }
            }
        }
    }
    #undef TG_LOAD
}

// ---------------------------------------------------------------------------
extern "C" void kernel_launch(void* const* d_in, const int* in_sizes, int n_in,
                              void* d_out, int out_size) {
    const float* x          = (const float*)d_in[0];
    const float* base_w     = (const float*)d_in[1];
    const float* base_b     = (const float*)d_in[2];
    const float* spectrum   = (const float*)d_in[3];
    const float* Blist      = (const float*)d_in[4];
    const float* gate_param = (const float*)d_in[5];
    const int*   idx_raw    = (const int*)d_in[6];
    const int*   gidx_raw   = (const int*)d_in[7];
    float* out = (float*)d_out;
    (void)in_sizes; (void)n_in; (void)out_size;

    __half *pPms, *pQns, *pW2s, *pZs, *pxh, *pwhp;
    cudaGetSymbolAddress((void**)&pPms, g_Pms);
    cudaGetSymbolAddress((void**)&pQns, g_Qns);
    cudaGetSymbolAddress((void**)&pW2s, g_W2s);
    cudaGetSymbolAddress((void**)&pZs,  g_Zs);
    cudaGetSymbolAddress((void**)&pxh,  g_xh);
    cudaGetSymbolAddress((void**)&pwhp, g_whp);

    cudaFuncSetAttribute(tgemm, cudaFuncAttributeMaxDynamicSharedMemorySize, SMEM_DYN);

    // 0..4: prep
    k_decode_idx<<<1, 256>>>(idx_raw, gidx_raw);
    k_gate_m<<<16, 256>>>(gate_param);
    k_gate_z<<<ROWS, 128>>>(x, Blist);     // gate weights + fp16 x + Z planes
    k_fill_trig<<<dim3(256, 2), 256>>>(spectrum);
    k_cast_wp<<<(int)(((ll)OO*DD)/256), 256>>>(base_w);

    // 5. 150*A_p = (150/2048^2) * Pm @ Qn^T -> fp16 W2s[o2][p*2048+d2]
    //    M=N=2048, K=2048, zbat=2 folded into grid.x
    tgemm<<<dim3(32, 16, 1), 128, SMEM_DYN>>>(
        pPms, HALF_D, (ll)HALF_D*HALF_D, pPms, 0ll,
        pQns, HALF_D, (ll)HALF_D*HALF_D, pQns, 0ll,
        pW2s, DD, 1, HALF_D,
        nullptr, 150.0f/4194304.0f, HALF_D, HALF_D, 1, 1);

    // 6. fused base+delta:
    //    out[row, 2n+z] = [xh | Z_z] @ [whp_z | W2]^T + b[2n+z]
    //    M=8192, N=2048, K=8192, zbat=2 folded into grid.x (parity-adjacent)
    tgemm<<<dim3(128, 16, 1), 128, SMEM_DYN>>>(
        pxh, DD, 0ll,            pZs,  (ll)ROWS*DD,
        pwhp, DD, (ll)HALF_D*DD, pW2s, 0ll,
        out, OO, 2, 1,
        base_b, 1.0f, 2*DD, DD, 1, 0);
}

// round 16
// speedup vs baseline: 1.2555x; 1.2555x over previous
#include <cuda_runtime.h>
#include <cuda_fp16.h>
#include <cstdint>

// ---------------------------------------------------------------------------
// KronFTLinear, fp16 mma.sync GEMMs (m16n8k16, f32 accum):
//   * base+delta FUSED into one K-concat GEMM:
//       out[row, 2n+z] = [xh | Z_z] @ [whp_z | W2]^T + b     (K = 8192)
//   * trig-GEMM scale 150 folded into stored W2.
// GEMM engine (R14, proven): 128x128x32 CTA tile, 4 warps of 64x64, 128
// threads, 3-stage cp.async pipeline (one __syncthreads per chunk),
// 2 CTAs/SM, L2 raster swizzle, parity batch z in fastest launch dim.
// R16: prep chain overlapped with trig GEMM via stream fork-join
// (capture-safe event pattern; streams created on first, non-captured call).
// ---------------------------------------------------------------------------

#define DD 4096
#define OO 4096
#define HALF_D 2048
#define NFP 1000
#define ROWS 8192
#define NGATE 819

typedef long long ll;

// ---------------- device scratch (no allocation allowed) -------------------
__device__ int   g_idx32[2*NFP];
__device__ int   g_gidx32[NGATE];
__device__ float g_gate_m[2*DD];
__device__ __half g_Pms[2ll*HALF_D*HALF_D];  // trig A-factor [p][m][k]
__device__ __half g_Qns[2ll*HALF_D*HALF_D];  // trig B-factor [p][n][k]
__device__ __half g_W2s[(ll)HALF_D*DD];      // 150 * A-matrix stack (fp16)
__device__ __half g_Zs[2ll*ROWS*DD];         // gated mixed x (fp16) [i][row][*]
__device__ __half g_xh[(ll)ROWS*DD];         // fp16 x
__device__ __half g_whp[(ll)OO*DD];          // fp16 base_w, parity-packed [z][n][k]

// ---------------- PTX helpers ----------------------------------------------
__device__ __forceinline__ uint32_t smem_u32(const void* p) {
    uint32_t a;
    asm("{ .reg .u64 t; cvta.to.shared.u64 t, %1; cvt.u32.u64 %0, t; }" : "=r"(a) : "l"(p));
    return a;
}
#define CP_ASYNC16(dst, src) \
    asm volatile("cp.async.cg.shared.global [%0], [%1], 16;" :: "r"(dst), "l"(src) : "memory")
#define CP_COMMIT() asm volatile("cp.async.commit_group;" ::: "memory")

#define LDSM_X4(r0, r1, r2, r3, addr) \
    asm volatile("ldmatrix.sync.aligned.m8n8.x4.shared.b16 {%0,%1,%2,%3}, [%4];" \
        : "=r"(r0), "=r"(r1), "=r"(r2), "=r"(r3) : "r"(addr))

#define MMA16816(c, a, b) \
    asm volatile("mma.sync.aligned.m16n8k16.row.col.f32.f16.f16.f32 " \
        "{%0,%1,%2,%3}, {%4,%5,%6,%7}, {%8,%9}, {%0,%1,%2,%3};" \
        : "+f"((c)[0]), "+f"((c)[1]), "+f"((c)[2]), "+f"((c)[3]) \
        : "r"((a)[0]), "r"((a)[1]), "r"((a)[2]), "r"((a)[3]), \
          "r"((b)[0]), "r"((b)[1]))

// ---------------- index decode: sniff int32 vs int64 -----------------------
__global__ void k_decode_idx(const int* __restrict__ idx_raw,
                             const int* __restrict__ gidx_raw) {
    __shared__ int nz;
    if (threadIdx.x == 0) nz = 0;
    __syncthreads();
    for (int k = threadIdx.x; k < NFP/2; k += 256)
        if (idx_raw[2*k + 1] != 0) atomicAdd(&nz, 1);
    __syncthreads();
    bool is64 = (nz == 0);
    for (int k = threadIdx.x; k < 2*NFP; k += 256)
        g_idx32[k] = is64 ? idx_raw[2*k] : idx_raw[k];
    for (int k = threadIdx.x; k < NGATE; k += 256)
        g_gidx32[k] = is64 ? gidx_raw[2*k] : gidx_raw[k];
}

// ---------------- gate matrix ----------------------------------------------
__global__ void k_gate_m(const float* __restrict__ gate_param) {
    __shared__ float tab[DD];
    __shared__ int   gc[NGATE];
    __shared__ float gg[NGATE], gs[NGATE];
    for (int t = threadIdx.x; t < DD; t += 256)
        tab[t] = cospif(t * (1.0f/2048.0f));
    for (int k = threadIdx.x; k < NGATE; k += 256) {
        int v = g_gidx32[k];
        int r = v >> 12;
        gc[k] = v & 4095;
        float g = gate_param[k];
        gg[k] = g;
        gs[k] = r ? -g : g;
    }
    __syncthreads();
    int d = blockIdx.x * 256 + threadIdx.x;
    float a0 = 0.f, a1 = 0.f;
    for (int k = 0; k < NGATE; k++) {
        int t = (d * gc[k]) & 4095;
        float co = tab[t];
        a0 += gg[k] * co;
        a1 += gs[k] * co;
    }
    g_gate_m[d]      = a0 * (1.0f/8192.0f);
    g_gate_m[DD + d] = a1 * (1.0f/8192.0f);
}

// ---------------- fused: gate weights + fp16 x cast + Z build --------------
__global__ __launch_bounds__(128)
void k_gate_z(const float* __restrict__ x, const float* __restrict__ Blist) {
    int row = blockIdx.x;
    int tid = threadIdx.x;
    const float2* xr = (const float2*)(x + (ll)row * DD);
    const float2* gm0 = (const float2*)g_gate_m;
    const float2* gm1 = (const float2*)(g_gate_m + DD);
    __half2* xhr = (__half2*)(g_xh + (ll)row * DD);

    float2 xv[16];
    float t0 = 0.f, t1 = 0.f;
    #pragma unroll
    for (int i = 0; i < 16; i++) {
        int d2 = tid + i*128;
        float2 v = xr[d2];
        xv[i] = v;
        xhr[d2] = __floats2half2_rn(v.x, v.y);
        float2 m0 = gm0[d2], m1 = gm1[d2];
        t0 += v.x*m0.x + v.y*m0.y;
        t1 += v.x*m1.x + v.y*m1.y;
    }

    __shared__ float s0[128], s1[128];
    __shared__ float sg[2];
    s0[tid] = t0; s1[tid] = t1;
    __syncthreads();
    for (int o = 64; o > 0; o >>= 1) {
        if (tid < o) { s0[tid] += s0[tid + o]; s1[tid] += s1[tid + o]; }
        __syncthreads();
    }
    if (tid == 0) {
        float g1 = 1.0f / (1.0f + expf(-(s1[0] - s0[0])));
        sg[0] = 1.0f - g1;
        sg[1] = g1;
    }
    __syncthreads();
    float g0 = sg[0], g1 = sg[1];

    float b0 = Blist[0], b1 = Blist[1], b2 = Blist[2], b3 = Blist[3];
    float b4 = Blist[4], b5 = Blist[5], b6 = Blist[6], b7 = Blist[7];
    const ll IOFF = (ll)ROWS * DD;
    ll base = (ll)row * DD;
    #pragma unroll
    for (int i = 0; i < 16; i++) {
        int d2 = tid + i*128;
        float xx = xv[i].x, yy = xv[i].y;
        g_Zs[base + d2]                 = __float2half(g0 * (b0*xx + b1*yy)); // i=0,p=0
        g_Zs[base + HALF_D + d2]        = __float2half(g1 * (b4*xx + b5*yy)); // i=0,p=1
        g_Zs[IOFF + base + d2]          = __float2half(g0 * (b2*xx + b3*yy)); // i=1,p=0
        g_Zs[IOFF + base + HALF_D + d2] = __float2half(g1 * (b6*xx + b7*yy)); // i=1,p=1
    }
}

// ---------------- trig factors, fp16 ----------------------------------------
__global__ void k_fill_trig(const float* __restrict__ spectrum) {
    __shared__ float tc[HALF_D], ts[HALF_D];
    __shared__ int   rr[NFP], cc[NFP];
    __shared__ float ss[NFP];
    int p = blockIdx.y;
    for (int t = threadIdx.x; t < HALF_D; t += 256) {
        float s, c;
        sincospif(t * (1.0f/1024.0f), &s, &c);
        tc[t] = c; ts[t] = s;
    }
    for (int k = threadIdx.x; k < NFP; k += 256) {
        int v = g_idx32[p*NFP + k];
        rr[k] = v >> 11;
        cc[k] = v & 2047;
        ss[k] = spectrum[p*NFP + k];
    }
    __syncthreads();
    int v0 = blockIdx.x * 8;
    for (int vi = 0; vi < 8; vi++) {
        int v = v0 + vi;
        ll base = ((ll)(p*HALF_D + v)) * HALF_D;
        for (int k = threadIdx.x; k < NFP; k += 256) {
            int tm = (v * rr[k]) & 2047;
            int tn = (v * cc[k]) & 2047;
            float s = ss[k];
            g_Pms[base + k]       = __float2half(s * tc[tm]);
            g_Pms[base + NFP + k] = __float2half(s * ts[tm]);
            g_Qns[base + k]       = __float2half(tc[tn]);
            g_Qns[base + NFP + k] = __float2half(-ts[tn]);
        }
        for (int k = 2*NFP + threadIdx.x; k < HALF_D; k += 256) {
            __half z = __float2half(0.f);
            g_Pms[base + k] = z;
            g_Qns[base + k] = z;
        }
    }
}

// ---------------- fp32 w -> fp16, parity-packed: whp[z][n][k] = w[2n+z][k] --
__global__ void k_cast_wp(const float* __restrict__ src) {
    ll i = (ll)blockIdx.x * 256 + threadIdx.x;
    int o = (int)(i >> 12);
    int k = (int)(i & 4095);
    int z = o & 1, n = o >> 1;
    g_whp[(ll)z*HALF_D*DD + (ll)n*DD + k] = __float2half(src[i]);
}

// ---------------- fp16 tensor-core GEMM with K-concat dual source ----------
// C = alpha * [A | A2] @ [B | B2]^T (+bias).  Source switches at Ksplit.
// 128x128x32 CTA tile, 4 warps (2x2) of 64x64, 128 threads, 3-stage cp.async
// (one __syncthreads per chunk), 2 CTAs/SM, L2 raster swizzle.
// Batch z folded into blockIdx.x (fastest dim).  Output (m,n,z) at
// C[m*ldc + n*cstride + z*czoff]; bias indexed bias[n*cstride + z*czoff].
#define STAGE_BYTES 20480u      // A(10240B) + B(10240B) per stage
#define SMEM_DYN (3*STAGE_BYTES)
#define GRP 8                   // m-tiles per L2 group

__global__ __launch_bounds__(128, 2)
void tgemm(const __half* __restrict__ A,  int lda, ll sAz,
           const __half* __restrict__ A2, ll sA2z,
           const __half* __restrict__ B,  int ldb, ll sBz,
           const __half* __restrict__ B2, ll sB2z,
           void* __restrict__ Cv, int ldc, int cstride, int czoff,
           const float* __restrict__ bias, float alpha,
           int Kp, int Ksplit, int zshift, int out_half)
{
    extern __shared__ char smem[];
    uint32_t sbase = smem_u32(smem);
    int tid = threadIdx.x, wid = tid >> 5, lane = tid & 31;
    int warpM = wid >> 1;          // 0..1  (64 rows)
    int warpN = wid & 1;           // 0..1  (64 cols)

    // z folded into fastest launch dim; then GRP raster swizzle on tile id
    int rawbid = blockIdx.y * gridDim.x + blockIdx.x;
    int z   = rawbid & ((1 << zshift) - 1);
    int fl2 = rawbid >> zshift;
    int tpg = GRP * gridDim.y;
    int grp = fl2 / tpg;
    int rem = fl2 - grp * tpg;
    int mt  = grp * GRP + (rem % GRP);
    int nt  = rem / GRP;

    ll m0 = (ll)mt * 128;
    ll n0 = (ll)nt * 128;
    const __half* Ab  = A  + (ll)z*sAz  + m0*lda;
    const __half* Ab2 = A2 + (ll)z*sA2z + m0*lda;
    const __half* Bb  = B  + (ll)z*sBz  + n0*ldb;
    const __half* Bb2 = B2 + (ll)z*sB2z + n0*ldb;

    float acc[4][8][4];
    #pragma unroll
    for (int i = 0; i < 4; i++)
        #pragma unroll
        for (int j = 0; j < 8; j++)
            #pragma unroll
            for (int q = 0; q < 4; q++) acc[i][j][q] = 0.f;

    int ldr = tid >> 2;            // 0..31
    int ldc8 = (tid & 3) * 8;      // 0,8,16,24

    int aRow = warpM*64 + (lane & 15);
    int aCsel = (lane >> 4) * 8;
    int bRowOff = (lane & 7) + ((lane >> 4) << 3);
    int bCsel = ((lane >> 3) & 1) * 8;

    int NP = Kp >> 5;

    #define TG_LOAD(stg, k0) do {                                              \
        const __half* _As; const __half* _Bs; int _ko;                         \
        if ((k0) < Ksplit) { _As = Ab;  _Bs = Bb;  _ko = (k0); }               \
        else               { _As = Ab2; _Bs = Bb2; _ko = (k0) - Ksplit; }      \
        uint32_t _sb = sbase + (uint32_t)(stg)*STAGE_BYTES;                    \
        uint32_t _da = _sb + (uint32_t)ldr*80 + (uint32_t)ldc8*2;              \
        uint32_t _db = _da + 10240u;                                           \
        _Pragma("unroll")                                                      \
        for (int _h = 0; _h < 4; _h++) {                                       \
            CP_ASYNC16(_da + _h*32*80, _As + (ll)(ldr + _h*32)*lda + _ko + ldc8); \
            CP_ASYNC16(_db + _h*32*80, _Bs + (ll)(ldr + _h*32)*ldb + _ko + ldc8); \
        }                                                                      \
        CP_COMMIT();                                                           \
    } while (0)

    TG_LOAD(0, 0);
    if (NP > 1) TG_LOAD(1, 32);

    int stg = 0;
    for (int kc = 0; kc < NP; kc++) {
        if (kc + 1 < NP) {
            asm volatile("cp.async.wait_group 1;" ::: "memory");
        } else {
            asm volatile("cp.async.wait_group 0;" ::: "memory");
        }
        __syncthreads();   // publishes chunk kc; proves all warps left stage (kc-1)%3
        if (kc + 2 < NP) {
            int ns = stg + 2; if (ns >= 3) ns -= 3;
            TG_LOAD(ns, (kc + 2) * 32);
        }

        uint32_t sao = sbase + (uint32_t)stg*STAGE_BYTES;
        uint32_t sbo = sao + 10240u;
        #pragma unroll
        for (int ks = 0; ks < 32; ks += 16) {
            uint32_t af[4][4];
            #pragma unroll
            for (int mi = 0; mi < 4; mi++) {
                uint32_t ad = sao + (uint32_t)(aRow + mi*16)*80 + (uint32_t)(ks + aCsel)*2;
                LDSM_X4(af[mi][0], af[mi][1], af[mi][2], af[mi][3], ad);
            }
            uint32_t bf[8][2];
            #pragma unroll
            for (int nj = 0; nj < 4; nj++) {
                uint32_t bd = sbo + (uint32_t)(warpN*64 + nj*16 + bRowOff)*80
                                  + (uint32_t)(ks + bCsel)*2;
                uint32_t r0, r1, r2, r3;
                LDSM_X4(r0, r1, r2, r3, bd);
                bf[nj*2][0] = r0;   bf[nj*2][1] = r1;
                bf[nj*2+1][0] = r2; bf[nj*2+1][1] = r3;
            }
            #pragma unroll
            for (int mi = 0; mi < 4; mi++)
                #pragma unroll
                for (int ni = 0; ni < 8; ni++)
                    MMA16816(acc[mi][ni], af[mi], bf[ni]);
        }
        if (++stg == 3) stg = 0;
    }

    // epilogue
    int gID = lane >> 2, tig = lane & 3;
    #pragma unroll
    for (int mi = 0; mi < 4; mi++) {
        #pragma unroll
        for (int h = 0; h < 2; h++) {
            ll row = m0 + warpM*64 + mi*16 + gID + h*8;
            ll rbase = row * (ll)ldc + (ll)z * czoff;
            #pragma unroll
            for (int ni = 0; ni < 8; ni++) {
                ll col0 = n0 + warpN*64 + ni*8 + tig*2;
                #pragma unroll
                for (int q = 0; q < 2; q++) {
                    ll col = col0 + q;
                    float v = acc[mi][ni][h*2 + q] * alpha;
                    ll coff = col * cstride + (ll)z * czoff;
                    if (bias) v += bias[coff];
                    ll off = rbase + col * cstride;
                    if (out_half) {
                        ((__half*)Cv)[off] = __float2half(v);
                    } else {
                        ((float*)Cv)[off] = v;
                    }
                }
            }
        }
    }
    #undef TG_LOAD
}

// ---------------------------------------------------------------------------
extern "C" void kernel_launch(void* const* d_in, const int* in_sizes, int n_in,
                              void* d_out, int out_size) {
    const float* x          = (const float*)d_in[0];
    const float* base_w     = (const float*)d_in[1];
    const float* base_b     = (const float*)d_in[2];
    const float* spectrum   = (const float*)d_in[3];
    const float* Blist      = (const float*)d_in[4];
    const float* gate_param = (const float*)d_in[5];
    const int*   idx_raw    = (const int*)d_in[6];
    const int*   gidx_raw   = (const int*)d_in[7];
    float* out = (float*)d_out;
    (void)in_sizes; (void)n_in; (void)out_size;

    __half *pPms, *pQns, *pW2s, *pZs, *pxh, *pwhp;
    cudaGetSymbolAddress((void**)&pPms, g_Pms);
    cudaGetSymbolAddress((void**)&pQns, g_Qns);
    cudaGetSymbolAddress((void**)&pW2s, g_W2s);
    cudaGetSymbolAddress((void**)&pZs,  g_Zs);
    cudaGetSymbolAddress((void**)&pxh,  g_xh);
    cudaGetSymbolAddress((void**)&pwhp, g_whp);

    cudaFuncSetAttribute(tgemm, cudaFuncAttributeMaxDynamicSharedMemorySize, SMEM_DYN);

    // Side streams + events, created once on the first (non-captured) call.
    static cudaStream_t s2 = nullptr, s3 = nullptr;
    static cudaEvent_t evStart, evA, evB, evC;
    if (s2 == nullptr) {
        cudaStreamCreateWithFlags(&s2, cudaStreamNonBlocking);
        cudaStreamCreateWithFlags(&s3, cudaStreamNonBlocking);
        cudaEventCreateWithFlags(&evStart, cudaEventDisableTiming);
        cudaEventCreateWithFlags(&evA,     cudaEventDisableTiming);
        cudaEventCreateWithFlags(&evB,     cudaEventDisableTiming);
        cudaEventCreateWithFlags(&evC,     cudaEventDisableTiming);
    }

    // ---- fork-join schedule ----
    // s0: decode -> gate_m -> gate_z            (gate path)
    // s2: (after decode) fill_trig -> trig GEMM (W2 path)
    // s3: (after start)  cast_wp                (weight cast)
    // s0 joins s2+s3, then runs the main fused GEMM.
    cudaEventRecord(evStart, 0);

    k_decode_idx<<<1, 256>>>(idx_raw, gidx_raw);
    cudaEventRecord(evA, 0);

    // s2: trig factor path
    cudaStreamWaitEvent(s2, evA, 0);
    k_fill_trig<<<dim3(256, 2), 256, 0, s2>>>(spectrum);
    tgemm<<<dim3(32, 16, 1), 128, SMEM_DYN, s2>>>(
        pPms, HALF_D, (ll)HALF_D*HALF_D, pPms, 0ll,
        pQns, HALF_D, (ll)HALF_D*HALF_D, pQns, 0ll,
        pW2s, DD, 1, HALF_D,
        nullptr, 150.0f/4194304.0f, HALF_D, HALF_D, 1, 1);
    cudaEventRecord(evB, s2);

    // s3: weight cast
    cudaStreamWaitEvent(s3, evStart, 0);
    k_cast_wp<<<(int)(((ll)OO*DD)/256), 256, 0, s3>>>(base_w);
    cudaEventRecord(evC, s3);

    // s0: gate path
    k_gate_m<<<16, 256>>>(gate_param);
    k_gate_z<<<ROWS, 128>>>(x, Blist);     // gate weights + fp16 x + Z planes

    // join
    cudaStreamWaitEvent(0, evB, 0);
    cudaStreamWaitEvent(0, evC, 0);

    // main fused base+delta GEMM:
    //   out[row, 2n+z] = [xh | Z_z] @ [whp_z | W2]^T + b[2n+z]
    //   M=8192, N=2048, K=8192, zbat=2 folded into grid.x (parity-adjacent)
    tgemm<<<dim3(128, 16, 1), 128, SMEM_DYN>>>(
        pxh, DD, 0ll,            pZs,  (ll)ROWS*DD,
        pwhp, DD, (ll)HALF_D*DD, pW2s, 0ll,
        out, OO, 2, 1,
        base_b, 1.0f, 2*DD, DD, 1, 0);
}